// round 3
// baseline (speedup 1.0000x reference)
#include <cuda_runtime.h>
#include <math.h>

#define SPLINE_ORDER 3
#define GRID_N   16
#define IN_DIM   64
#define OUT_DIM  64
#define BATCH    1024
#define NCOEF    (GRID_N + SPLINE_ORDER)   // 19

#define BT 32                // batch tile = warp lanes
#define OB 4                 // o-columns per block
#define THREADS 256
#define PITCH4 17            // float4 row pitch (16 data + 1 pad)

#define NPACK  (OUT_DIM * IN_DIM * GRID_N)   // 65536
#define NBI    (BATCH * IN_DIM)              // 65536

// Scratch (__device__ globals; no allocation in kernel_launch):
__device__ float4 g_packed[NPACK];        // packed[o][i][m] = coef[o,i,m..m+3]  (1 MB)
__device__ float4 g_w4t[NBI];             // w4t[i][b] = 4 spline weights        (1 MB)
__device__ int    g_i0t[NBI];             // i0t[i][b] = knot interval           (256 KB)

// Fused prep: pack coef rows + per-(b,i) closed-form uniform cubic B-spline weights.
__global__ void prep_kernel(const float* __restrict__ coef,
                            const float* __restrict__ x,
                            const float* __restrict__ grid) {
    int p = blockIdx.x * blockDim.x + threadIdx.x;
    if (p < NPACK) {
        int m  = p & (GRID_N - 1);
        int oi = p >> 4;
        const float* c = coef + oi * NCOEF + m;
        g_packed[p] = make_float4(c[0], c[1], c[2], c[3]);
    } else if (p < NPACK + NBI) {
        int w = p - NPACK;
        int i = w >> 10;            // w4t is [i][b] (transposed for coalesced reads)
        int b = w & (BATCH - 1);
        const float g3    = grid[SPLINE_ORDER];
        const float inv_h = 1.0f / (grid[SPLINE_ORDER + 1] - g3);
        const float k6    = 1.0f / 6.0f;
        const float xv = x[b * IN_DIM + i];   // scattered read (tiny kernel, fine)
        float t = (xv - g3) * inv_h;
        int i0 = (int)floorf(t);
        i0 = min(GRID_N - 1, max(0, i0));
        const float u  = t - (float)i0;
        const float om = 1.0f - u;
        const float u2 = u * u;
        float4 wv;
        wv.x = om * om * om * k6;
        wv.w = u2 * u * k6;
        wv.y = fmaf(u2, fmaf(0.5f, u, -1.0f), 2.0f / 3.0f);
        wv.z = 1.0f - wv.x - wv.y - wv.w;
        g_w4t[w] = wv;
        g_i0t[w] = i0;
    }
}

__global__ __launch_bounds__(THREADS)
void kan_kernel(float* __restrict__ out) {
    __shared__ float4 S4[OB * BT * PITCH4];        // [oo][b][i4], pitch 17

    const int b0 = (blockIdx.x & 31) * BT;         // 32 batch tiles
    const int o0 = (blockIdx.x >> 5) * OB;         // 16 o-chunks

    const int lane = threadIdx.x & 31;   // -> batch within tile
    const int warp = threadIdx.x >> 5;   // -> i-group (8 i's per warp)

    #pragma unroll
    for (int g = 0; g < 2; g++) {
        const int ibase = warp * 8 + g * 4;
        const int i4    = warp * 2 + g;

        // Coalesced per-(b,i) weights + knot rows (prep-computed; no barrier needed).
        float4 w[4];
        const float4* pr[4];
        #pragma unroll
        for (int j = 0; j < 4; j++) {
            int idx = (ibase + j) * BATCH + b0 + lane;
            w[j]  = g_w4t[idx];
            pr[j] = g_packed + (size_t)(o0 * IN_DIM + ibase + j) * GRID_N + g_i0t[idx];
        }

        #pragma unroll
        for (int oo = 0; oo < OB; oo++) {
            // 4 independent LDG.128, each warp-load within one 256B coef row (lanes=b).
            float4 c0 = pr[0][oo * (IN_DIM * GRID_N)];
            float4 c1 = pr[1][oo * (IN_DIM * GRID_N)];
            float4 c2 = pr[2][oo * (IN_DIM * GRID_N)];
            float4 c3 = pr[3][oo * (IN_DIM * GRID_N)];
            float4 r;
            r.x = fmaf(w[0].w, c0.w, fmaf(w[0].z, c0.z, fmaf(w[0].y, c0.y, w[0].x * c0.x)));
            r.y = fmaf(w[1].w, c1.w, fmaf(w[1].z, c1.z, fmaf(w[1].y, c1.y, w[1].x * c1.x)));
            r.z = fmaf(w[2].w, c2.w, fmaf(w[2].z, c2.z, fmaf(w[2].y, c2.y, w[2].x * c2.x)));
            r.w = fmaf(w[3].w, c3.w, fmaf(w[3].z, c3.z, fmaf(w[3].y, c3.y, w[3].x * c3.x)));
            S4[(oo * BT + lane) * PITCH4 + i4] = r;   // STS.128, phase-conflict-free
        }
    }
    __syncthreads();

    // Transposed store: 2048 float4s, 8 per thread, coalesced STG.128.
    #pragma unroll
    for (int k = 0; k < 8; k++) {
        int t  = threadIdx.x + k * THREADS;
        int i4 = t & 15;
        int oo = (t >> 4) & 3;
        int bb = t >> 6;
        float4 v = S4[(oo * BT + bb) * PITCH4 + i4];  // LDS.128, conflict-free
        reinterpret_cast<float4*>(out)[((size_t)(b0 + bb) * OUT_DIM + (o0 + oo)) * (IN_DIM / 4) + i4] = v;
    }
}

extern "C" void kernel_launch(void* const* d_in, const int* in_sizes, int n_in,
                              void* d_out, int out_size) {
    const float* x    = (const float*)d_in[0];
    const float* coef = (const float*)d_in[1];
    const float* grid = (const float*)d_in[2];
    float* out        = (float*)d_out;

    prep_kernel<<<(NPACK + NBI + 255) / 256, 256>>>(coef, x, grid);
    kan_kernel<<<(BATCH / BT) * (OUT_DIM / OB), THREADS>>>(out);
}

// round 5
// speedup vs baseline: 1.4000x; 1.4000x over previous
#include <cuda_runtime.h>
#include <math.h>

#define SPLINE_ORDER 3
#define GRID_N   16
#define IN_DIM   64
#define OUT_DIM  64
#define BATCH    1024
#define NCOEF    (GRID_N + SPLINE_ORDER)   // 19

#define BT 32                 // batch tile (warp lanes = b)
#define OB 4                  // o-columns per block
#define THREADS 256
#define PITCH4 17             // float4 transpose pitch (16 data + 1 pad)

#define CS_FLOATS (OB * IN_DIM * NCOEF)        // 4864  (19456 B)
#define XS_FLOATS (BT * 65)                    // 2080  ( 8320 B)
#define S4_FLOAT4 (OB * BT * PITCH4)           // 2176  (34816 B)
#define SMEM_BYTES ((CS_FLOATS + XS_FLOATS) * 4 + S4_FLOAT4 * 16)   // 62592

__global__ __launch_bounds__(THREADS)
void kan_kernel(const float* __restrict__ x,
                const float* __restrict__ coef,
                const float* __restrict__ grid,
                float* __restrict__ out) {
    extern __shared__ float sm[];
    float*  cs = sm;                                   // coef tile [oo][i][19]
    float*  xs = sm + CS_FLOATS;                       // x tile [b][i], pitch 65
    float4* S4 = (float4*)(sm + CS_FLOATS + XS_FLOATS); // results [oo][b][i4]

    const int b0 = (blockIdx.x & 31) * BT;             // 32 batch tiles
    const int o0 = (blockIdx.x >> 5) * OB;             // 16 o-chunks
    const int lane = threadIdx.x & 31;                 // -> b
    const int warp = threadIdx.x >> 5;                 // -> i-group of 8

    // ---- Stage coef tile (contiguous, 16B-aligned) + x tile, both coalesced.
    {
        const float4* src = (const float4*)(coef + (size_t)o0 * IN_DIM * NCOEF);
        #pragma unroll
        for (int t = threadIdx.x; t < CS_FLOATS / 4; t += THREADS)
            ((float4*)cs)[t] = src[t];
        #pragma unroll
        for (int t = threadIdx.x; t < BT * IN_DIM; t += THREADS) {
            int bb = t >> 6, i = t & 63;
            xs[bb * 65 + i] = x[(b0 + bb) * IN_DIM + i];
        }
    }
    const float g3    = grid[SPLINE_ORDER];
    const float inv_h = 1.0f / (grid[SPLINE_ORDER + 1] - g3);
    const float k6    = 1.0f / 6.0f;
    __syncthreads();

    // ---- Compute: 2 i-quads per thread, gather coef from SMEM (conflict-free).
    #pragma unroll
    for (int g = 0; g < 2; g++) {
        const int ibase = warp * 8 + g * 4;
        const int i4    = warp * 2 + g;

        float w0[4], w1[4], w2[4], w3[4];
        int   base[4];
        #pragma unroll
        for (int j = 0; j < 4; j++) {
            const float xv = xs[lane * 65 + ibase + j];
            float t = (xv - g3) * inv_h;
            int i0 = (int)floorf(t);
            i0 = min(GRID_N - 1, max(0, i0));
            const float u  = t - (float)i0;
            const float om = 1.0f - u;
            const float u2 = u * u;
            w0[j] = om * om * om * k6;
            w3[j] = u2 * u * k6;
            w1[j] = fmaf(u2, fmaf(0.5f, u, -1.0f), 2.0f / 3.0f);
            w2[j] = 1.0f - w0[j] - w1[j] - w3[j];
            base[j] = (ibase + j) * NCOEF + i0;
        }

        #pragma unroll
        for (int oo = 0; oo < OB; oo++) {
            const float* c = cs + oo * (IN_DIM * NCOEF);
            float4 r;
            // lanes=b: addresses span <32 words per LDS -> bank-conflict-free.
            r.x = fmaf(w3[0], c[base[0] + 3], fmaf(w2[0], c[base[0] + 2],
                  fmaf(w1[0], c[base[0] + 1], w0[0] * c[base[0]])));
            r.y = fmaf(w3[1], c[base[1] + 3], fmaf(w2[1], c[base[1] + 2],
                  fmaf(w1[1], c[base[1] + 1], w0[1] * c[base[1]])));
            r.z = fmaf(w3[2], c[base[2] + 3], fmaf(w2[2], c[base[2] + 2],
                  fmaf(w1[2], c[base[2] + 1], w0[2] * c[base[2]])));
            r.w = fmaf(w3[3], c[base[3] + 3], fmaf(w2[3], c[base[3] + 2],
                  fmaf(w1[3], c[base[3] + 1], w0[3] * c[base[3]])));
            S4[(oo * BT + lane) * PITCH4 + i4] = r;   // STS.128, phase-conflict-free
        }
    }
    __syncthreads();

    // ---- Transposed store: 2048 float4s, 8 per thread, coalesced STG.128.
    #pragma unroll
    for (int k = 0; k < 8; k++) {
        int t  = threadIdx.x + k * THREADS;
        int i4 = t & 15;
        int oo = (t >> 4) & 3;
        int bb = t >> 6;
        float4 v = S4[(oo * BT + bb) * PITCH4 + i4];  // LDS.128, conflict-free
        reinterpret_cast<float4*>(out)[((size_t)(b0 + bb) * OUT_DIM + (o0 + oo)) * (IN_DIM / 4) + i4] = v;
    }
}

extern "C" void kernel_launch(void* const* d_in, const int* in_sizes, int n_in,
                              void* d_out, int out_size) {
    const float* x    = (const float*)d_in[0];
    const float* coef = (const float*)d_in[1];
    const float* grid = (const float*)d_in[2];
    float* out        = (float*)d_out;

    cudaFuncSetAttribute(kan_kernel, cudaFuncAttributeMaxDynamicSharedMemorySize,
                         SMEM_BYTES);
    kan_kernel<<<(BATCH / BT) * (OUT_DIM / OB), THREADS, SMEM_BYTES>>>(x, coef, grid, out);
}